// round 15
// baseline (speedup 1.0000x reference)
#include <cuda_runtime.h>
#include <cstdint>

#define N_NODES 100000
#define N_EDGES 300000
#define HID 32

// Scratch (device globals; no allocation allowed). 16B-aligned for v4 access.
__device__ __align__(16) float g_agg1[N_NODES * HID];  // layer1 accumulator; k3 re-zeroes after read
__device__ __align__(16) float g_uvw[N_NODES * 96];    // per-node rows: [u(32) | v(32) | w(32)]
__device__ __align__(16) float g_agg2[N_NODES * HID];  // layer2 accumulator

__device__ __forceinline__ void red_add_v4(float* addr, float a, float b, float c, float d) {
    asm volatile("red.global.add.v4.f32 [%0], {%1,%2,%3,%4};"
                 :: "l"(addr), "f"(a), "f"(b), "f"(c), "f"(d) : "memory");
}

__device__ __forceinline__ uint32_t to_tf32(float f) {
    uint32_t r; asm("cvt.rna.tf32.f32 %0, %1;" : "=r"(r) : "f"(f)); return r;
}

__device__ __forceinline__ void mma_tf32_16n8k8(float c[4],
                                                uint32_t a0, uint32_t a1, uint32_t a2, uint32_t a3,
                                                uint32_t b0, uint32_t b1) {
    asm volatile(
        "mma.sync.aligned.m16n8k8.row.col.f32.tf32.tf32.f32 "
        "{%0,%1,%2,%3}, {%4,%5,%6,%7}, {%8,%9}, {%0,%1,%2,%3};"
        : "+f"(c[0]), "+f"(c[1]), "+f"(c[2]), "+f"(c[3])
        : "r"(a0), "r"(a1), "r"(a2), "r"(a3), "r"(b0), "r"(b1));
}

// ---------------------------------------------------------------------------
// K2: layer-1 edge messages. 4 edges per thread, 4 channels each.
// ---------------------------------------------------------------------------
__global__ void k2_edges1(const int* __restrict__ ei,
                          const float* __restrict__ ea,
                          const float* __restrict__ nn1_w,
                          const float* __restrict__ nn1_b,
                          const float* __restrict__ x) {
    int t = blockIdx.x * blockDim.x + threadIdx.x;
    if (t >= N_EDGES * 2) return;
    int e = (t >> 3) * 4;
    int q = (t & 7) * 4;
    int4   ss   = *reinterpret_cast<const int4*>(&ei[e]);
    int4   dd   = *reinterpret_cast<const int4*>(&ei[N_EDGES + e]);
    float4 ea01 = *reinterpret_cast<const float4*>(&ea[2 * e]);
    float4 ea23 = *reinterpret_cast<const float4*>(&ea[2 * e + 4]);
    float2 x0 = *reinterpret_cast<const float2*>(&x[ss.x * 2]);
    float2 x1 = *reinterpret_cast<const float2*>(&x[ss.y * 2]);
    float2 x2 = *reinterpret_cast<const float2*>(&x[ss.z * 2]);
    float2 x3 = *reinterpret_cast<const float2*>(&x[ss.w * 2]);

    float m0[4], m1[4], m2[4], m3[4];
#pragma unroll
    for (int c = 0; c < 4; c++) {
        int ch = q + c, ch2 = ch + HID;
        float wA0 = nn1_w[2 * ch + 0],  wA1 = nn1_w[2 * ch + 1],  bA = nn1_b[ch];
        float wB0 = nn1_w[2 * ch2 + 0], wB1 = nn1_w[2 * ch2 + 1], bB = nn1_b[ch2];
        {
            float wa = fmaf(wA0, ea01.x, fmaf(wA1, ea01.y, bA));
            float wb = fmaf(wB0, ea01.x, fmaf(wB1, ea01.y, bB));
            m0[c] = fmaf(x0.x, wa, x0.y * wb);
        }
        {
            float wa = fmaf(wA0, ea01.z, fmaf(wA1, ea01.w, bA));
            float wb = fmaf(wB0, ea01.z, fmaf(wB1, ea01.w, bB));
            m1[c] = fmaf(x1.x, wa, x1.y * wb);
        }
        {
            float wa = fmaf(wA0, ea23.x, fmaf(wA1, ea23.y, bA));
            float wb = fmaf(wB0, ea23.x, fmaf(wB1, ea23.y, bB));
            m2[c] = fmaf(x2.x, wa, x2.y * wb);
        }
        {
            float wa = fmaf(wA0, ea23.z, fmaf(wA1, ea23.w, bA));
            float wb = fmaf(wB0, ea23.z, fmaf(wB1, ea23.w, bB));
            m3[c] = fmaf(x3.x, wa, x3.y * wb);
        }
    }
    red_add_v4(&g_agg1[dd.x * HID + q], m0[0], m0[1], m0[2], m0[3]);
    red_add_v4(&g_agg1[dd.y * HID + q], m1[0], m1[1], m1[2], m1[3]);
    red_add_v4(&g_agg1[dd.z * HID + q], m2[0], m2[1], m2[2], m2[3]);
    red_add_v4(&g_agg1[dd.w * HID + q], m3[0], m3[1], m3[2], m3[3]);
}

// ---------------------------------------------------------------------------
// K3: tensor-core (tf32 mma.sync) per-node precompute for layer 2 (R8 form).
//   H[128x32] = relu(agg1 + x@root1 + bias1); Wcat[32x128] = [A | B | C | root2]
//   D = H @ Wcat -> chans 0-95 -> g_uvw ; chans 96-127 (+bias2) -> g_agg2
// RE-ZEROES g_agg1 after reading (replaces the memset graph node; the array
// is zero at module load, so the invariant holds for every execution).
// ---------------------------------------------------------------------------
__global__ void k3_node2(const float* __restrict__ x,
                         const float* __restrict__ root1,
                         const float* __restrict__ bias1,
                         const float* __restrict__ nn2_w,
                         const float* __restrict__ nn2_b,
                         const float* __restrict__ root2,
                         const float* __restrict__ bias2) {
    __shared__ uint32_t sH[128 * 36];   // tf32 H: sH[m*36 + k]
    __shared__ uint32_t sW[32 * 136];   // tf32 Wcat: sW[k*136 + chan]
    __shared__ float sB2[32], sR1[64], sB1[32];
    int tid = threadIdx.x;
    if (tid < 64) sR1[tid] = root1[tid];
    if (tid < 32) { sB1[tid] = bias1[tid]; sB2[tid] = bias2[tid]; }
    __syncthreads();

    for (int idx = tid; idx < 32 * 128; idx += 256) {
        int k = idx >> 7, c = idx & 127;
        float w;
        if (c < 32)       w = nn2_w[(k * 32 + c) * 2 + 0];
        else if (c < 64)  w = nn2_w[(k * 32 + c - 32) * 2 + 1];
        else if (c < 96)  w = nn2_b[k * 32 + c - 64];
        else              w = root2[k * 32 + c - 96];
        sW[k * 136 + c] = to_tf32(w);
    }

    int blockBase = blockIdx.x * 128;
    for (int idx = tid; idx < 128 * 32; idx += 256) {
        int m = idx >> 5, kk = idx & 31;
        int n = blockBase + m;
        float val = 0.0f;
        if (n < N_NODES) {
            float2 xv = *reinterpret_cast<const float2*>(&x[n * 2]);
            float root = fmaf(xv.x, sR1[kk], fmaf(xv.y, sR1[HID + kk], sB1[kk]));
            int gi = n * HID + kk;
            val = fmaxf(g_agg1[gi] + root, 0.0f);
            g_agg1[gi] = 0.0f;      // re-zero for the next graph execution
        }
        sH[m * 36 + kk] = to_tf32(val);
    }
    __syncthreads();

    int warp = tid >> 5, lane = tid & 31;
    int gid = lane >> 2, tig = lane & 3;
    int mloc = warp * 16;

    uint32_t a[4][4];
#pragma unroll
    for (int kc = 0; kc < 4; kc++) {
        int k0 = kc * 8 + tig;
        a[kc][0] = sH[(mloc + gid) * 36 + k0];
        a[kc][1] = sH[(mloc + gid + 8) * 36 + k0];
        a[kc][2] = sH[(mloc + gid) * 36 + k0 + 4];
        a[kc][3] = sH[(mloc + gid + 8) * 36 + k0 + 4];
    }

    int node0 = blockBase + mloc + gid;
    int node1 = node0 + 8;
#pragma unroll
    for (int nt = 0; nt < 16; nt++) {
        float c[4] = {0.0f, 0.0f, 0.0f, 0.0f};
#pragma unroll
        for (int kc = 0; kc < 4; kc++) {
            uint32_t b0 = sW[(kc * 8 + tig) * 136 + nt * 8 + gid];
            uint32_t b1 = sW[(kc * 8 + tig + 4) * 136 + nt * 8 + gid];
            mma_tf32_16n8k8(c, a[kc][0], a[kc][1], a[kc][2], a[kc][3], b0, b1);
        }
        int chan = nt * 8 + tig * 2;
        if (nt < 12) {
            if (node0 < N_NODES)
                *reinterpret_cast<float2*>(&g_uvw[node0 * 96 + chan]) = make_float2(c[0], c[1]);
            if (node1 < N_NODES)
                *reinterpret_cast<float2*>(&g_uvw[node1 * 96 + chan]) = make_float2(c[2], c[3]);
        } else {
            int cb = chan - 96;
            float b0f = sB2[cb], b1f = sB2[cb + 1];
            if (node0 < N_NODES)
                *reinterpret_cast<float2*>(&g_agg2[node0 * HID + cb]) = make_float2(c[0] + b0f, c[1] + b1f);
            if (node1 < N_NODES)
                *reinterpret_cast<float2*>(&g_agg2[node1 * HID + cb]) = make_float2(c[2] + b0f, c[3] + b1f);
        }
    }
}

// ---------------------------------------------------------------------------
// K4: layer-2 edge messages. 4 edges per thread, 4 channels (float4) each.
// fp32 planar uvw (R13): every load instruction is a single-line coalesced
// wavefront; 12 independent gathers batched up front.
// ---------------------------------------------------------------------------
__global__ void k4_edges2(const int* __restrict__ ei,
                          const float* __restrict__ ea) {
    int t = blockIdx.x * blockDim.x + threadIdx.x;
    if (t >= N_EDGES * 2) return;
    int e = (t >> 3) * 4;
    int q = (t & 7) * 4;
    int4   ss   = *reinterpret_cast<const int4*>(&ei[e]);
    int4   dd   = *reinterpret_cast<const int4*>(&ei[N_EDGES + e]);
    float4 ea01 = *reinterpret_cast<const float4*>(&ea[2 * e]);
    float4 ea23 = *reinterpret_cast<const float4*>(&ea[2 * e + 4]);

    const float* b0p = g_uvw + ss.x * 96 + q;
    const float* b1p = g_uvw + ss.y * 96 + q;
    const float* b2p = g_uvw + ss.z * 96 + q;
    const float* b3p = g_uvw + ss.w * 96 + q;
    float4 u0 = *reinterpret_cast<const float4*>(b0p);
    float4 v0 = *reinterpret_cast<const float4*>(b0p + 32);
    float4 w0 = *reinterpret_cast<const float4*>(b0p + 64);
    float4 u1 = *reinterpret_cast<const float4*>(b1p);
    float4 v1 = *reinterpret_cast<const float4*>(b1p + 32);
    float4 w1 = *reinterpret_cast<const float4*>(b1p + 64);
    float4 u2 = *reinterpret_cast<const float4*>(b2p);
    float4 v2 = *reinterpret_cast<const float4*>(b2p + 32);
    float4 w2 = *reinterpret_cast<const float4*>(b2p + 64);
    float4 u3 = *reinterpret_cast<const float4*>(b3p);
    float4 v3 = *reinterpret_cast<const float4*>(b3p + 32);
    float4 w3 = *reinterpret_cast<const float4*>(b3p + 64);

    float a0 = fmaf(ea01.x, u0.x, fmaf(ea01.y, v0.x, w0.x));
    float a1 = fmaf(ea01.x, u0.y, fmaf(ea01.y, v0.y, w0.y));
    float a2 = fmaf(ea01.x, u0.z, fmaf(ea01.y, v0.z, w0.z));
    float a3 = fmaf(ea01.x, u0.w, fmaf(ea01.y, v0.w, w0.w));
    red_add_v4(&g_agg2[dd.x * HID + q], a0, a1, a2, a3);

    float b0 = fmaf(ea01.z, u1.x, fmaf(ea01.w, v1.x, w1.x));
    float b1 = fmaf(ea01.z, u1.y, fmaf(ea01.w, v1.y, w1.y));
    float b2 = fmaf(ea01.z, u1.z, fmaf(ea01.w, v1.z, w1.z));
    float b3 = fmaf(ea01.z, u1.w, fmaf(ea01.w, v1.w, w1.w));
    red_add_v4(&g_agg2[dd.y * HID + q], b0, b1, b2, b3);

    float c0 = fmaf(ea23.x, u2.x, fmaf(ea23.y, v2.x, w2.x));
    float c1 = fmaf(ea23.x, u2.y, fmaf(ea23.y, v2.y, w2.y));
    float c2 = fmaf(ea23.x, u2.z, fmaf(ea23.y, v2.z, w2.z));
    float c3 = fmaf(ea23.x, u2.w, fmaf(ea23.y, v2.w, w2.w));
    red_add_v4(&g_agg2[dd.z * HID + q], c0, c1, c2, c3);

    float d0 = fmaf(ea23.z, u3.x, fmaf(ea23.w, v3.x, w3.x));
    float d1 = fmaf(ea23.z, u3.y, fmaf(ea23.w, v3.y, w3.y));
    float d2 = fmaf(ea23.z, u3.z, fmaf(ea23.w, v3.z, w3.z));
    float d3 = fmaf(ea23.z, u3.w, fmaf(ea23.w, v3.w, w3.w));
    red_add_v4(&g_agg2[dd.w * HID + q], d0, d1, d2, d3);
}

// ---------------------------------------------------------------------------
// K5: epilogue, thread-per-node (EXACT R8 config).
// ---------------------------------------------------------------------------
#define K5_NODES 256
__global__ void k5_final(const float* __restrict__ fc1_w,
                         const float* __restrict__ fc1_b,
                         const float* __restrict__ fc2_w,
                         const float* __restrict__ fc2_b,
                         float* __restrict__ out) {
    __shared__ float sW[HID * HID];        // fc1_w, row-major (as-is)
    __shared__ float sb[HID];
    __shared__ float sf2[HID];
    __shared__ float sH[K5_NODES * 36];    // padded h2 rows
    int tid = threadIdx.x;
    for (int k = tid; k < HID * HID; k += 256) sW[k] = fc1_w[k];   // coalesced
    if (tid < HID) { sb[tid] = fc1_b[tid]; sf2[tid] = fc2_w[tid]; }

    int base = blockIdx.x * K5_NODES;
    for (int k = tid; k < K5_NODES * HID; k += 256) {
        int nl = k >> 5, i = k & 31;
        int n = base + nl;
        float v = 0.0f;
        if (n < N_NODES) v = fmaxf(g_agg2[n * HID + i], 0.0f);     // coalesced
        sH[nl * 36 + i] = v;                                        // conflict-free
    }
    __syncthreads();

    float4 h4[8];
    const float4* hp = reinterpret_cast<const float4*>(&sH[tid * 36]);
#pragma unroll
    for (int i = 0; i < 8; i++) h4[i] = hp[i];

    const float4* w4 = reinterpret_cast<const float4*>(sW);
    float total = 0.0f;
#pragma unroll 4
    for (int o = 0; o < HID; o++) {
        float a0 = sb[o], a1 = 0.0f, a2 = 0.0f, a3 = 0.0f;
#pragma unroll
        for (int i = 0; i < 8; i++) {
            float4 w = w4[o * 8 + i];   // broadcast LDS.128 (1 wavefront)
            a0 = fmaf(h4[i].x, w.x, a0);
            a1 = fmaf(h4[i].y, w.y, a1);
            a2 = fmaf(h4[i].z, w.z, a2);
            a3 = fmaf(h4[i].w, w.w, a3);
        }
        float acc = (a0 + a1) + (a2 + a3);
        total = fmaf(fmaxf(acc, 0.0f), sf2[o], total);
    }
    int n = base + tid;
    if (n < N_NODES) out[n] = total + fc2_b[0];
}

// ---------------------------------------------------------------------------
extern "C" void kernel_launch(void* const* d_in, const int* in_sizes, int n_in,
                              void* d_out, int out_size) {
    const float* x       = (const float*)d_in[0];
    const int*   ei      = (const int*)  d_in[1];
    const float* ea      = (const float*)d_in[2];
    const float* nn1_w   = (const float*)d_in[3];
    const float* nn1_b   = (const float*)d_in[4];
    const float* root1   = (const float*)d_in[5];
    const float* bias1   = (const float*)d_in[6];
    const float* nn2_w   = (const float*)d_in[7];
    const float* nn2_b   = (const float*)d_in[8];
    const float* root2   = (const float*)d_in[9];
    const float* bias2   = (const float*)d_in[10];
    const float* fc1_w   = (const float*)d_in[11];
    const float* fc1_b   = (const float*)d_in[12];
    const float* fc2_w   = (const float*)d_in[13];
    const float* fc2_b   = (const float*)d_in[14];
    float* out = (float*)d_out;

    const int tpb = 256;
    int gridEdge = (N_EDGES * 2 + tpb - 1) / tpb;         // 2344
    int gridK3   = (N_NODES + 127) / 128;                 // 782
    int gridK5   = (N_NODES + K5_NODES - 1) / K5_NODES;   // 391

    k2_edges1<<<gridEdge, tpb>>>(ei, ea, nn1_w, nn1_b, x);
    k3_node2<<<gridK3, tpb>>>(x, root1, bias1, nn2_w, nn2_b, root2, bias2);
    k4_edges2<<<gridEdge, tpb>>>(ei, ea);
    k5_final<<<gridK5, tpb>>>(fc1_w, fc1_b, fc2_w, fc2_b, out);
}

// round 16
// speedup vs baseline: 1.7671x; 1.7671x over previous
#include <cuda_runtime.h>
#include <cstdint>

#define N_NODES 100000
#define N_EDGES 300000
#define HID 32

// Scratch (device globals; no allocation allowed). 16B-aligned for v4 access.
// g_agg1 is zero at module load; k5 (graph-final kernel) re-zeroes it each
// execution, so k2 always sees zeros AND the lines are L2-warm at k2 entry.
__device__ __align__(16) float g_agg1[N_NODES * HID];
__device__ __align__(16) float g_uvw[N_NODES * 96];    // per-node rows: [u(32) | v(32) | w(32)]
__device__ __align__(16) float g_agg2[N_NODES * HID];  // layer2 accumulator

__device__ __forceinline__ void red_add_v4(float* addr, float a, float b, float c, float d) {
    asm volatile("red.global.add.v4.f32 [%0], {%1,%2,%3,%4};"
                 :: "l"(addr), "f"(a), "f"(b), "f"(c), "f"(d) : "memory");
}

__device__ __forceinline__ uint32_t to_tf32(float f) {
    uint32_t r; asm("cvt.rna.tf32.f32 %0, %1;" : "=r"(r) : "f"(f)); return r;
}

__device__ __forceinline__ void mma_tf32_16n8k8(float c[4],
                                                uint32_t a0, uint32_t a1, uint32_t a2, uint32_t a3,
                                                uint32_t b0, uint32_t b1) {
    asm volatile(
        "mma.sync.aligned.m16n8k8.row.col.f32.tf32.tf32.f32 "
        "{%0,%1,%2,%3}, {%4,%5,%6,%7}, {%8,%9}, {%0,%1,%2,%3};"
        : "+f"(c[0]), "+f"(c[1]), "+f"(c[2]), "+f"(c[3])
        : "r"(a0), "r"(a1), "r"(a2), "r"(a3), "r"(b0), "r"(b1));
}

// ---------------------------------------------------------------------------
// K2: layer-1 edge messages. 4 edges per thread, 4 channels each.
// ---------------------------------------------------------------------------
__global__ void k2_edges1(const int* __restrict__ ei,
                          const float* __restrict__ ea,
                          const float* __restrict__ nn1_w,
                          const float* __restrict__ nn1_b,
                          const float* __restrict__ x) {
    int t = blockIdx.x * blockDim.x + threadIdx.x;
    if (t >= N_EDGES * 2) return;
    int e = (t >> 3) * 4;
    int q = (t & 7) * 4;
    int4   ss   = *reinterpret_cast<const int4*>(&ei[e]);
    int4   dd   = *reinterpret_cast<const int4*>(&ei[N_EDGES + e]);
    float4 ea01 = *reinterpret_cast<const float4*>(&ea[2 * e]);
    float4 ea23 = *reinterpret_cast<const float4*>(&ea[2 * e + 4]);
    float2 x0 = *reinterpret_cast<const float2*>(&x[ss.x * 2]);
    float2 x1 = *reinterpret_cast<const float2*>(&x[ss.y * 2]);
    float2 x2 = *reinterpret_cast<const float2*>(&x[ss.z * 2]);
    float2 x3 = *reinterpret_cast<const float2*>(&x[ss.w * 2]);

    float m0[4], m1[4], m2[4], m3[4];
#pragma unroll
    for (int c = 0; c < 4; c++) {
        int ch = q + c, ch2 = ch + HID;
        float wA0 = nn1_w[2 * ch + 0],  wA1 = nn1_w[2 * ch + 1],  bA = nn1_b[ch];
        float wB0 = nn1_w[2 * ch2 + 0], wB1 = nn1_w[2 * ch2 + 1], bB = nn1_b[ch2];
        {
            float wa = fmaf(wA0, ea01.x, fmaf(wA1, ea01.y, bA));
            float wb = fmaf(wB0, ea01.x, fmaf(wB1, ea01.y, bB));
            m0[c] = fmaf(x0.x, wa, x0.y * wb);
        }
        {
            float wa = fmaf(wA0, ea01.z, fmaf(wA1, ea01.w, bA));
            float wb = fmaf(wB0, ea01.z, fmaf(wB1, ea01.w, bB));
            m1[c] = fmaf(x1.x, wa, x1.y * wb);
        }
        {
            float wa = fmaf(wA0, ea23.x, fmaf(wA1, ea23.y, bA));
            float wb = fmaf(wB0, ea23.x, fmaf(wB1, ea23.y, bB));
            m2[c] = fmaf(x2.x, wa, x2.y * wb);
        }
        {
            float wa = fmaf(wA0, ea23.z, fmaf(wA1, ea23.w, bA));
            float wb = fmaf(wB0, ea23.z, fmaf(wB1, ea23.w, bB));
            m3[c] = fmaf(x3.x, wa, x3.y * wb);
        }
    }
    red_add_v4(&g_agg1[dd.x * HID + q], m0[0], m0[1], m0[2], m0[3]);
    red_add_v4(&g_agg1[dd.y * HID + q], m1[0], m1[1], m1[2], m1[3]);
    red_add_v4(&g_agg1[dd.z * HID + q], m2[0], m2[1], m2[2], m2[3]);
    red_add_v4(&g_agg1[dd.w * HID + q], m3[0], m3[1], m3[2], m3[3]);
}

// ---------------------------------------------------------------------------
// K3: tensor-core (tf32 mma.sync) per-node precompute for layer 2 (R8 form).
//   H[128x32] = relu(agg1 + x@root1 + bias1); Wcat[32x128] = [A | B | C | root2]
//   D = H @ Wcat -> chans 0-95 -> g_uvw ; chans 96-127 (+bias2) -> g_agg2
// (Does NOT zero g_agg1 — that happens in k5 so the lines stay L2-warm for
//  the next replay's k2.)
// ---------------------------------------------------------------------------
__global__ void k3_node2(const float* __restrict__ x,
                         const float* __restrict__ root1,
                         const float* __restrict__ bias1,
                         const float* __restrict__ nn2_w,
                         const float* __restrict__ nn2_b,
                         const float* __restrict__ root2,
                         const float* __restrict__ bias2) {
    __shared__ uint32_t sH[128 * 36];   // tf32 H: sH[m*36 + k]
    __shared__ uint32_t sW[32 * 136];   // tf32 Wcat: sW[k*136 + chan]
    __shared__ float sB2[32], sR1[64], sB1[32];
    int tid = threadIdx.x;
    if (tid < 64) sR1[tid] = root1[tid];
    if (tid < 32) { sB1[tid] = bias1[tid]; sB2[tid] = bias2[tid]; }
    __syncthreads();

    for (int idx = tid; idx < 32 * 128; idx += 256) {
        int k = idx >> 7, c = idx & 127;
        float w;
        if (c < 32)       w = nn2_w[(k * 32 + c) * 2 + 0];
        else if (c < 64)  w = nn2_w[(k * 32 + c - 32) * 2 + 1];
        else if (c < 96)  w = nn2_b[k * 32 + c - 64];
        else              w = root2[k * 32 + c - 96];
        sW[k * 136 + c] = to_tf32(w);
    }

    int blockBase = blockIdx.x * 128;
    for (int idx = tid; idx < 128 * 32; idx += 256) {
        int m = idx >> 5, kk = idx & 31;
        int n = blockBase + m;
        float val = 0.0f;
        if (n < N_NODES) {
            float2 xv = *reinterpret_cast<const float2*>(&x[n * 2]);
            float root = fmaf(xv.x, sR1[kk], fmaf(xv.y, sR1[HID + kk], sB1[kk]));
            val = fmaxf(g_agg1[n * HID + kk] + root, 0.0f);
        }
        sH[m * 36 + kk] = to_tf32(val);
    }
    __syncthreads();

    int warp = tid >> 5, lane = tid & 31;
    int gid = lane >> 2, tig = lane & 3;
    int mloc = warp * 16;

    uint32_t a[4][4];
#pragma unroll
    for (int kc = 0; kc < 4; kc++) {
        int k0 = kc * 8 + tig;
        a[kc][0] = sH[(mloc + gid) * 36 + k0];
        a[kc][1] = sH[(mloc + gid + 8) * 36 + k0];
        a[kc][2] = sH[(mloc + gid) * 36 + k0 + 4];
        a[kc][3] = sH[(mloc + gid + 8) * 36 + k0 + 4];
    }

    int node0 = blockBase + mloc + gid;
    int node1 = node0 + 8;
#pragma unroll
    for (int nt = 0; nt < 16; nt++) {
        float c[4] = {0.0f, 0.0f, 0.0f, 0.0f};
#pragma unroll
        for (int kc = 0; kc < 4; kc++) {
            uint32_t b0 = sW[(kc * 8 + tig) * 136 + nt * 8 + gid];
            uint32_t b1 = sW[(kc * 8 + tig + 4) * 136 + nt * 8 + gid];
            mma_tf32_16n8k8(c, a[kc][0], a[kc][1], a[kc][2], a[kc][3], b0, b1);
        }
        int chan = nt * 8 + tig * 2;
        if (nt < 12) {
            if (node0 < N_NODES)
                *reinterpret_cast<float2*>(&g_uvw[node0 * 96 + chan]) = make_float2(c[0], c[1]);
            if (node1 < N_NODES)
                *reinterpret_cast<float2*>(&g_uvw[node1 * 96 + chan]) = make_float2(c[2], c[3]);
        } else {
            int cb = chan - 96;
            float b0f = sB2[cb], b1f = sB2[cb + 1];
            if (node0 < N_NODES)
                *reinterpret_cast<float2*>(&g_agg2[node0 * HID + cb]) = make_float2(c[0] + b0f, c[1] + b1f);
            if (node1 < N_NODES)
                *reinterpret_cast<float2*>(&g_agg2[node1 * HID + cb]) = make_float2(c[2] + b0f, c[3] + b1f);
        }
    }
}

// ---------------------------------------------------------------------------
// K4: layer-2 edge messages. 4 edges per thread, 4 channels (float4) each.
// ---------------------------------------------------------------------------
__global__ void k4_edges2(const int* __restrict__ ei,
                          const float* __restrict__ ea) {
    int t = blockIdx.x * blockDim.x + threadIdx.x;
    if (t >= N_EDGES * 2) return;
    int e = (t >> 3) * 4;
    int q = (t & 7) * 4;
    int4   ss   = *reinterpret_cast<const int4*>(&ei[e]);
    int4   dd   = *reinterpret_cast<const int4*>(&ei[N_EDGES + e]);
    float4 ea01 = *reinterpret_cast<const float4*>(&ea[2 * e]);
    float4 ea23 = *reinterpret_cast<const float4*>(&ea[2 * e + 4]);

    const float* b0p = g_uvw + ss.x * 96 + q;
    const float* b1p = g_uvw + ss.y * 96 + q;
    const float* b2p = g_uvw + ss.z * 96 + q;
    const float* b3p = g_uvw + ss.w * 96 + q;
    float4 u0 = *reinterpret_cast<const float4*>(b0p);
    float4 v0 = *reinterpret_cast<const float4*>(b0p + 32);
    float4 w0 = *reinterpret_cast<const float4*>(b0p + 64);
    float4 u1 = *reinterpret_cast<const float4*>(b1p);
    float4 v1 = *reinterpret_cast<const float4*>(b1p + 32);
    float4 w1 = *reinterpret_cast<const float4*>(b1p + 64);
    float4 u2 = *reinterpret_cast<const float4*>(b2p);
    float4 v2 = *reinterpret_cast<const float4*>(b2p + 32);
    float4 w2 = *reinterpret_cast<const float4*>(b2p + 64);
    float4 u3 = *reinterpret_cast<const float4*>(b3p);
    float4 v3 = *reinterpret_cast<const float4*>(b3p + 32);
    float4 w3 = *reinterpret_cast<const float4*>(b3p + 64);

    float a0 = fmaf(ea01.x, u0.x, fmaf(ea01.y, v0.x, w0.x));
    float a1 = fmaf(ea01.x, u0.y, fmaf(ea01.y, v0.y, w0.y));
    float a2 = fmaf(ea01.x, u0.z, fmaf(ea01.y, v0.z, w0.z));
    float a3 = fmaf(ea01.x, u0.w, fmaf(ea01.y, v0.w, w0.w));
    red_add_v4(&g_agg2[dd.x * HID + q], a0, a1, a2, a3);

    float b0 = fmaf(ea01.z, u1.x, fmaf(ea01.w, v1.x, w1.x));
    float b1 = fmaf(ea01.z, u1.y, fmaf(ea01.w, v1.y, w1.y));
    float b2 = fmaf(ea01.z, u1.z, fmaf(ea01.w, v1.z, w1.z));
    float b3 = fmaf(ea01.z, u1.w, fmaf(ea01.w, v1.w, w1.w));
    red_add_v4(&g_agg2[dd.y * HID + q], b0, b1, b2, b3);

    float c0 = fmaf(ea23.x, u2.x, fmaf(ea23.y, v2.x, w2.x));
    float c1 = fmaf(ea23.x, u2.y, fmaf(ea23.y, v2.y, w2.y));
    float c2 = fmaf(ea23.x, u2.z, fmaf(ea23.y, v2.z, w2.z));
    float c3 = fmaf(ea23.x, u2.w, fmaf(ea23.y, v2.w, w2.w));
    red_add_v4(&g_agg2[dd.z * HID + q], c0, c1, c2, c3);

    float d0 = fmaf(ea23.z, u3.x, fmaf(ea23.w, v3.x, w3.x));
    float d1 = fmaf(ea23.z, u3.y, fmaf(ea23.w, v3.y, w3.y));
    float d2 = fmaf(ea23.z, u3.z, fmaf(ea23.w, v3.z, w3.z));
    float d3 = fmaf(ea23.z, u3.w, fmaf(ea23.w, v3.w, w3.w));
    red_add_v4(&g_agg2[dd.w * HID + q], d0, d1, d2, d3);
}

// ---------------------------------------------------------------------------
// K5: epilogue, thread-per-node (R8 config) + re-zero g_agg1 for the next
// graph execution. k5 is the LAST kernel, so the zeroed lines remain L2-warm
// when the next replay's k2 issues its atomics (the R15 experiment showed
// mid-graph zeroing gets evicted and costs ~50us of cold-line atomic fills).
// ---------------------------------------------------------------------------
#define K5_NODES 256
__global__ void k5_final(const float* __restrict__ fc1_w,
                         const float* __restrict__ fc1_b,
                         const float* __restrict__ fc2_w,
                         const float* __restrict__ fc2_b,
                         float* __restrict__ out) {
    __shared__ float sW[HID * HID];        // fc1_w, row-major (as-is)
    __shared__ float sb[HID];
    __shared__ float sf2[HID];
    __shared__ float sH[K5_NODES * 36];    // padded h2 rows
    int tid = threadIdx.x;
    for (int k = tid; k < HID * HID; k += 256) sW[k] = fc1_w[k];   // coalesced
    if (tid < HID) { sb[tid] = fc1_b[tid]; sf2[tid] = fc2_w[tid]; }

    int base = blockIdx.x * K5_NODES;
    for (int k = tid; k < K5_NODES * HID; k += 256) {
        int nl = k >> 5, i = k & 31;
        int n = base + nl;
        float v = 0.0f;
        if (n < N_NODES) v = fmaxf(g_agg2[n * HID + i], 0.0f);     // coalesced
        sH[nl * 36 + i] = v;                                        // conflict-free
    }
    // Re-zero this block's slice of g_agg1 (float4 stores, coalesced).
    {
        float4 z = make_float4(0.0f, 0.0f, 0.0f, 0.0f);
        int sliceBase = base * HID / 4;                 // in float4 units
        int sliceLen  = K5_NODES * HID / 4;             // 2048 float4 per block
        int totalLen  = N_NODES * HID / 4;
        float4* a1 = reinterpret_cast<float4*>(g_agg1);
        for (int k = tid; k < sliceLen; k += 256) {
            int idx = sliceBase + k;
            if (idx < totalLen) a1[idx] = z;
        }
    }
    __syncthreads();

    float4 h4[8];
    const float4* hp = reinterpret_cast<const float4*>(&sH[tid * 36]);
#pragma unroll
    for (int i = 0; i < 8; i++) h4[i] = hp[i];

    const float4* w4 = reinterpret_cast<const float4*>(sW);
    float total = 0.0f;
#pragma unroll 4
    for (int o = 0; o < HID; o++) {
        float a0 = sb[o], a1 = 0.0f, a2 = 0.0f, a3 = 0.0f;
#pragma unroll
        for (int i = 0; i < 8; i++) {
            float4 w = w4[o * 8 + i];   // broadcast LDS.128 (1 wavefront)
            a0 = fmaf(h4[i].x, w.x, a0);
            a1 = fmaf(h4[i].y, w.y, a1);
            a2 = fmaf(h4[i].z, w.z, a2);
            a3 = fmaf(h4[i].w, w.w, a3);
        }
        float acc = (a0 + a1) + (a2 + a3);
        total = fmaf(fmaxf(acc, 0.0f), sf2[o], total);
    }
    int n = base + tid;
    if (n < N_NODES) out[n] = total + fc2_b[0];
}

// ---------------------------------------------------------------------------
extern "C" void kernel_launch(void* const* d_in, const int* in_sizes, int n_in,
                              void* d_out, int out_size) {
    const float* x       = (const float*)d_in[0];
    const int*   ei      = (const int*)  d_in[1];
    const float* ea      = (const float*)d_in[2];
    const float* nn1_w   = (const float*)d_in[3];
    const float* nn1_b   = (const float*)d_in[4];
    const float* root1   = (const float*)d_in[5];
    const float* bias1   = (const float*)d_in[6];
    const float* nn2_w   = (const float*)d_in[7];
    const float* nn2_b   = (const float*)d_in[8];
    const float* root2   = (const float*)d_in[9];
    const float* bias2   = (const float*)d_in[10];
    const float* fc1_w   = (const float*)d_in[11];
    const float* fc1_b   = (const float*)d_in[12];
    const float* fc2_w   = (const float*)d_in[13];
    const float* fc2_b   = (const float*)d_in[14];
    float* out = (float*)d_out;

    const int tpb = 256;
    int gridEdge = (N_EDGES * 2 + tpb - 1) / tpb;         // 2344
    int gridK3   = (N_NODES + 127) / 128;                 // 782
    int gridK5   = (N_NODES + K5_NODES - 1) / K5_NODES;   // 391

    k2_edges1<<<gridEdge, tpb>>>(ei, ea, nn1_w, nn1_b, x);
    k3_node2<<<gridK3, tpb>>>(x, root1, bias1, nn2_w, nn2_b, root2, bias2);
    k4_edges2<<<gridEdge, tpb>>>(ei, ea);
    k5_final<<<gridK5, tpb>>>(fc1_w, fc1_b, fc2_w, fc2_b, out);
}

// round 17
// speedup vs baseline: 1.9000x; 1.0752x over previous
#include <cuda_runtime.h>
#include <cstdint>

#define N_NODES 100000
#define N_EDGES 300000
#define HID 32

// Scratch (device globals; no allocation allowed). 16B-aligned for v4 access.
// g_agg1 is zero at module load; k5 (graph-final kernel) re-zeroes it each
// execution, so k2 always sees zeros AND the lines are L2-warm at k2 entry.
__device__ __align__(16) float g_agg1[N_NODES * HID];
__device__ __align__(16) float g_uvw[N_NODES * 96];    // per-node rows: [u(32) | v(32) | w(32)]
__device__ __align__(16) float g_agg2[N_NODES * HID];  // layer2 accumulator

__device__ __forceinline__ void red_add_v4(float* addr, float a, float b, float c, float d) {
    asm volatile("red.global.add.v4.f32 [%0], {%1,%2,%3,%4};"
                 :: "l"(addr), "f"(a), "f"(b), "f"(c), "f"(d) : "memory");
}

__device__ __forceinline__ uint32_t to_tf32(float f) {
    uint32_t r; asm("cvt.rna.tf32.f32 %0, %1;" : "=r"(r) : "f"(f)); return r;
}

__device__ __forceinline__ void mma_tf32_16n8k8(float c[4],
                                                uint32_t a0, uint32_t a1, uint32_t a2, uint32_t a3,
                                                uint32_t b0, uint32_t b1) {
    asm volatile(
        "mma.sync.aligned.m16n8k8.row.col.f32.tf32.tf32.f32 "
        "{%0,%1,%2,%3}, {%4,%5,%6,%7}, {%8,%9}, {%0,%1,%2,%3};"
        : "+f"(c[0]), "+f"(c[1]), "+f"(c[2]), "+f"(c[3])
        : "r"(a0), "r"(a1), "r"(a2), "r"(a3), "r"(b0), "r"(b1));
}

// ---------------------------------------------------------------------------
// K2: layer-1 edge messages. 4 edges per thread, 4 channels each.
// ---------------------------------------------------------------------------
__global__ void k2_edges1(const int* __restrict__ ei,
                          const float* __restrict__ ea,
                          const float* __restrict__ nn1_w,
                          const float* __restrict__ nn1_b,
                          const float* __restrict__ x) {
    int t = blockIdx.x * blockDim.x + threadIdx.x;
    if (t >= N_EDGES * 2) return;
    int e = (t >> 3) * 4;
    int q = (t & 7) * 4;
    int4   ss   = *reinterpret_cast<const int4*>(&ei[e]);
    int4   dd   = *reinterpret_cast<const int4*>(&ei[N_EDGES + e]);
    float4 ea01 = *reinterpret_cast<const float4*>(&ea[2 * e]);
    float4 ea23 = *reinterpret_cast<const float4*>(&ea[2 * e + 4]);
    float2 x0 = *reinterpret_cast<const float2*>(&x[ss.x * 2]);
    float2 x1 = *reinterpret_cast<const float2*>(&x[ss.y * 2]);
    float2 x2 = *reinterpret_cast<const float2*>(&x[ss.z * 2]);
    float2 x3 = *reinterpret_cast<const float2*>(&x[ss.w * 2]);

    float m0[4], m1[4], m2[4], m3[4];
#pragma unroll
    for (int c = 0; c < 4; c++) {
        int ch = q + c, ch2 = ch + HID;
        float wA0 = nn1_w[2 * ch + 0],  wA1 = nn1_w[2 * ch + 1],  bA = nn1_b[ch];
        float wB0 = nn1_w[2 * ch2 + 0], wB1 = nn1_w[2 * ch2 + 1], bB = nn1_b[ch2];
        {
            float wa = fmaf(wA0, ea01.x, fmaf(wA1, ea01.y, bA));
            float wb = fmaf(wB0, ea01.x, fmaf(wB1, ea01.y, bB));
            m0[c] = fmaf(x0.x, wa, x0.y * wb);
        }
        {
            float wa = fmaf(wA0, ea01.z, fmaf(wA1, ea01.w, bA));
            float wb = fmaf(wB0, ea01.z, fmaf(wB1, ea01.w, bB));
            m1[c] = fmaf(x1.x, wa, x1.y * wb);
        }
        {
            float wa = fmaf(wA0, ea23.x, fmaf(wA1, ea23.y, bA));
            float wb = fmaf(wB0, ea23.x, fmaf(wB1, ea23.y, bB));
            m2[c] = fmaf(x2.x, wa, x2.y * wb);
        }
        {
            float wa = fmaf(wA0, ea23.z, fmaf(wA1, ea23.w, bA));
            float wb = fmaf(wB0, ea23.z, fmaf(wB1, ea23.w, bB));
            m3[c] = fmaf(x3.x, wa, x3.y * wb);
        }
    }
    red_add_v4(&g_agg1[dd.x * HID + q], m0[0], m0[1], m0[2], m0[3]);
    red_add_v4(&g_agg1[dd.y * HID + q], m1[0], m1[1], m1[2], m1[3]);
    red_add_v4(&g_agg1[dd.z * HID + q], m2[0], m2[1], m2[2], m2[3]);
    red_add_v4(&g_agg1[dd.w * HID + q], m3[0], m3[1], m3[2], m3[3]);
}

// ---------------------------------------------------------------------------
// K3: tensor-core (tf32 mma.sync) per-node precompute for layer 2.
// PERSISTENT over tiles: weights staged ONCE per block, then loop over
// 128-node tiles strided by gridDim (cuts weight re-staging ~40%).
// ---------------------------------------------------------------------------
#define K3_TILES ((N_NODES + 127) / 128)   // 782
__global__ void k3_node2(const float* __restrict__ x,
                         const float* __restrict__ root1,
                         const float* __restrict__ bias1,
                         const float* __restrict__ nn2_w,
                         const float* __restrict__ nn2_b,
                         const float* __restrict__ root2,
                         const float* __restrict__ bias2) {
    __shared__ uint32_t sH[128 * 36];   // tf32 H: sH[m*36 + k]
    __shared__ uint32_t sW[32 * 136];   // tf32 Wcat: sW[k*136 + chan]
    __shared__ float sB2[32], sR1[64], sB1[32];
    int tid = threadIdx.x;
    if (tid < 64) sR1[tid] = root1[tid];
    if (tid < 32) { sB1[tid] = bias1[tid]; sB2[tid] = bias2[tid]; }

    for (int idx = tid; idx < 32 * 128; idx += 256) {
        int k = idx >> 7, c = idx & 127;
        float w;
        if (c < 32)       w = nn2_w[(k * 32 + c) * 2 + 0];
        else if (c < 64)  w = nn2_w[(k * 32 + c - 32) * 2 + 1];
        else if (c < 96)  w = nn2_b[k * 32 + c - 64];
        else              w = root2[k * 32 + c - 96];
        sW[k * 136 + c] = to_tf32(w);
    }

    int warp = tid >> 5, lane = tid & 31;
    int gid = lane >> 2, tig = lane & 3;
    int mloc = warp * 16;

    for (int tile = blockIdx.x; tile < K3_TILES; tile += gridDim.x) {
        int blockBase = tile * 128;
        __syncthreads();   // weights ready (iter 0) / prev tile's sH reads done
        for (int idx = tid; idx < 128 * 32; idx += 256) {
            int m = idx >> 5, kk = idx & 31;
            int n = blockBase + m;
            float val = 0.0f;
            if (n < N_NODES) {
                float2 xv = *reinterpret_cast<const float2*>(&x[n * 2]);
                float root = fmaf(xv.x, sR1[kk], fmaf(xv.y, sR1[HID + kk], sB1[kk]));
                val = fmaxf(g_agg1[n * HID + kk] + root, 0.0f);
            }
            sH[m * 36 + kk] = to_tf32(val);
        }
        __syncthreads();

        uint32_t a[4][4];
#pragma unroll
        for (int kc = 0; kc < 4; kc++) {
            int k0 = kc * 8 + tig;
            a[kc][0] = sH[(mloc + gid) * 36 + k0];
            a[kc][1] = sH[(mloc + gid + 8) * 36 + k0];
            a[kc][2] = sH[(mloc + gid) * 36 + k0 + 4];
            a[kc][3] = sH[(mloc + gid + 8) * 36 + k0 + 4];
        }

        int node0 = blockBase + mloc + gid;
        int node1 = node0 + 8;
#pragma unroll
        for (int nt = 0; nt < 16; nt++) {
            float c[4] = {0.0f, 0.0f, 0.0f, 0.0f};
#pragma unroll
            for (int kc = 0; kc < 4; kc++) {
                uint32_t b0 = sW[(kc * 8 + tig) * 136 + nt * 8 + gid];
                uint32_t b1 = sW[(kc * 8 + tig + 4) * 136 + nt * 8 + gid];
                mma_tf32_16n8k8(c, a[kc][0], a[kc][1], a[kc][2], a[kc][3], b0, b1);
            }
            int chan = nt * 8 + tig * 2;
            if (nt < 12) {
                if (node0 < N_NODES)
                    *reinterpret_cast<float2*>(&g_uvw[node0 * 96 + chan]) = make_float2(c[0], c[1]);
                if (node1 < N_NODES)
                    *reinterpret_cast<float2*>(&g_uvw[node1 * 96 + chan]) = make_float2(c[2], c[3]);
            } else {
                int cb = chan - 96;
                float b0f = sB2[cb], b1f = sB2[cb + 1];
                if (node0 < N_NODES)
                    *reinterpret_cast<float2*>(&g_agg2[node0 * HID + cb]) = make_float2(c[0] + b0f, c[1] + b1f);
                if (node1 < N_NODES)
                    *reinterpret_cast<float2*>(&g_agg2[node1 * HID + cb]) = make_float2(c[2] + b0f, c[3] + b1f);
            }
        }
    }
}

// ---------------------------------------------------------------------------
// K4: layer-2 edge messages. 4 edges per thread, 4 channels (float4) each.
// ---------------------------------------------------------------------------
__global__ void k4_edges2(const int* __restrict__ ei,
                          const float* __restrict__ ea) {
    int t = blockIdx.x * blockDim.x + threadIdx.x;
    if (t >= N_EDGES * 2) return;
    int e = (t >> 3) * 4;
    int q = (t & 7) * 4;
    int4   ss   = *reinterpret_cast<const int4*>(&ei[e]);
    int4   dd   = *reinterpret_cast<const int4*>(&ei[N_EDGES + e]);
    float4 ea01 = *reinterpret_cast<const float4*>(&ea[2 * e]);
    float4 ea23 = *reinterpret_cast<const float4*>(&ea[2 * e + 4]);

    const float* b0p = g_uvw + ss.x * 96 + q;
    const float* b1p = g_uvw + ss.y * 96 + q;
    const float* b2p = g_uvw + ss.z * 96 + q;
    const float* b3p = g_uvw + ss.w * 96 + q;
    float4 u0 = *reinterpret_cast<const float4*>(b0p);
    float4 v0 = *reinterpret_cast<const float4*>(b0p + 32);
    float4 w0 = *reinterpret_cast<const float4*>(b0p + 64);
    float4 u1 = *reinterpret_cast<const float4*>(b1p);
    float4 v1 = *reinterpret_cast<const float4*>(b1p + 32);
    float4 w1 = *reinterpret_cast<const float4*>(b1p + 64);
    float4 u2 = *reinterpret_cast<const float4*>(b2p);
    float4 v2 = *reinterpret_cast<const float4*>(b2p + 32);
    float4 w2 = *reinterpret_cast<const float4*>(b2p + 64);
    float4 u3 = *reinterpret_cast<const float4*>(b3p);
    float4 v3 = *reinterpret_cast<const float4*>(b3p + 32);
    float4 w3 = *reinterpret_cast<const float4*>(b3p + 64);

    float a0 = fmaf(ea01.x, u0.x, fmaf(ea01.y, v0.x, w0.x));
    float a1 = fmaf(ea01.x, u0.y, fmaf(ea01.y, v0.y, w0.y));
    float a2 = fmaf(ea01.x, u0.z, fmaf(ea01.y, v0.z, w0.z));
    float a3 = fmaf(ea01.x, u0.w, fmaf(ea01.y, v0.w, w0.w));
    red_add_v4(&g_agg2[dd.x * HID + q], a0, a1, a2, a3);

    float b0 = fmaf(ea01.z, u1.x, fmaf(ea01.w, v1.x, w1.x));
    float b1 = fmaf(ea01.z, u1.y, fmaf(ea01.w, v1.y, w1.y));
    float b2 = fmaf(ea01.z, u1.z, fmaf(ea01.w, v1.z, w1.z));
    float b3 = fmaf(ea01.z, u1.w, fmaf(ea01.w, v1.w, w1.w));
    red_add_v4(&g_agg2[dd.y * HID + q], b0, b1, b2, b3);

    float c0 = fmaf(ea23.x, u2.x, fmaf(ea23.y, v2.x, w2.x));
    float c1 = fmaf(ea23.x, u2.y, fmaf(ea23.y, v2.y, w2.y));
    float c2 = fmaf(ea23.x, u2.z, fmaf(ea23.y, v2.z, w2.z));
    float c3 = fmaf(ea23.x, u2.w, fmaf(ea23.y, v2.w, w2.w));
    red_add_v4(&g_agg2[dd.z * HID + q], c0, c1, c2, c3);

    float d0 = fmaf(ea23.z, u3.x, fmaf(ea23.w, v3.x, w3.x));
    float d1 = fmaf(ea23.z, u3.y, fmaf(ea23.w, v3.y, w3.y));
    float d2 = fmaf(ea23.z, u3.z, fmaf(ea23.w, v3.z, w3.z));
    float d3 = fmaf(ea23.z, u3.w, fmaf(ea23.w, v3.w, w3.w));
    red_add_v4(&g_agg2[dd.w * HID + q], d0, d1, d2, d3);
}

// ---------------------------------------------------------------------------
// K5: epilogue, thread-per-node + re-zero g_agg1 (graph-final => L2-warm for
// next replay's k2). __launch_bounds__(256,3): kernel is GRID-limited
// (391 blocks = 2.64/SM), so allowing ~85 regs costs no occupancy and lets
// ptxas pipeline the LDS->FMA chains; o-loop unroll widened to 8.
// ---------------------------------------------------------------------------
#define K5_NODES 256
__global__ void __launch_bounds__(256, 3)
k5_final(const float* __restrict__ fc1_w,
         const float* __restrict__ fc1_b,
         const float* __restrict__ fc2_w,
         const float* __restrict__ fc2_b,
         float* __restrict__ out) {
    __shared__ float sW[HID * HID];        // fc1_w, row-major (as-is)
    __shared__ float sb[HID];
    __shared__ float sf2[HID];
    __shared__ float sH[K5_NODES * 36];    // padded h2 rows
    int tid = threadIdx.x;
    for (int k = tid; k < HID * HID; k += 256) sW[k] = fc1_w[k];   // coalesced
    if (tid < HID) { sb[tid] = fc1_b[tid]; sf2[tid] = fc2_w[tid]; }

    int base = blockIdx.x * K5_NODES;
    for (int k = tid; k < K5_NODES * HID; k += 256) {
        int nl = k >> 5, i = k & 31;
        int n = base + nl;
        float v = 0.0f;
        if (n < N_NODES) v = fmaxf(g_agg2[n * HID + i], 0.0f);     // coalesced
        sH[nl * 36 + i] = v;                                        // conflict-free
    }
    // Re-zero this block's slice of g_agg1 (float4 stores, coalesced).
    {
        float4 z = make_float4(0.0f, 0.0f, 0.0f, 0.0f);
        int sliceBase = base * HID / 4;
        int sliceLen  = K5_NODES * HID / 4;
        int totalLen  = N_NODES * HID / 4;
        float4* a1 = reinterpret_cast<float4*>(g_agg1);
        for (int k = tid; k < sliceLen; k += 256) {
            int idx = sliceBase + k;
            if (idx < totalLen) a1[idx] = z;
        }
    }
    __syncthreads();

    float4 h4[8];
    const float4* hp = reinterpret_cast<const float4*>(&sH[tid * 36]);
#pragma unroll
    for (int i = 0; i < 8; i++) h4[i] = hp[i];

    const float4* w4 = reinterpret_cast<const float4*>(sW);
    float total = 0.0f;
#pragma unroll 8
    for (int o = 0; o < HID; o++) {
        float a0 = sb[o], a1 = 0.0f, a2 = 0.0f, a3 = 0.0f;
#pragma unroll
        for (int i = 0; i < 8; i++) {
            float4 w = w4[o * 8 + i];   // broadcast LDS.128 (1 wavefront)
            a0 = fmaf(h4[i].x, w.x, a0);
            a1 = fmaf(h4[i].y, w.y, a1);
            a2 = fmaf(h4[i].z, w.z, a2);
            a3 = fmaf(h4[i].w, w.w, a3);
        }
        float acc = (a0 + a1) + (a2 + a3);
        total = fmaf(fmaxf(acc, 0.0f), sf2[o], total);
    }
    int n = base + tid;
    if (n < N_NODES) out[n] = total + fc2_b[0];
}

// ---------------------------------------------------------------------------
extern "C" void kernel_launch(void* const* d_in, const int* in_sizes, int n_in,
                              void* d_out, int out_size) {
    const float* x       = (const float*)d_in[0];
    const int*   ei      = (const int*)  d_in[1];
    const float* ea      = (const float*)d_in[2];
    const float* nn1_w   = (const float*)d_in[3];
    const float* nn1_b   = (const float*)d_in[4];
    const float* root1   = (const float*)d_in[5];
    const float* bias1   = (const float*)d_in[6];
    const float* nn2_w   = (const float*)d_in[7];
    const float* nn2_b   = (const float*)d_in[8];
    const float* root2   = (const float*)d_in[9];
    const float* bias2   = (const float*)d_in[10];
    const float* fc1_w   = (const float*)d_in[11];
    const float* fc1_b   = (const float*)d_in[12];
    const float* fc2_w   = (const float*)d_in[13];
    const float* fc2_b   = (const float*)d_in[14];
    float* out = (float*)d_out;

    const int tpb = 256;
    int gridEdge = (N_EDGES * 2 + tpb - 1) / tpb;         // 2344
    int gridK3   = 444;                                   // persistent: 3 per SM
    int gridK5   = (N_NODES + K5_NODES - 1) / K5_NODES;   // 391

    k2_edges1<<<gridEdge, tpb>>>(ei, ea, nn1_w, nn1_b, x);
    k3_node2<<<gridK3, tpb>>>(x, root1, bias1, nn2_w, nn2_b, root2, bias2);
    k4_edges2<<<gridEdge, tpb>>>(ei, ea);
    k5_final<<<gridK5, tpb>>>(fc1_w, fc1_b, fc2_w, fc2_b, out);
}